// round 10
// baseline (speedup 1.0000x reference)
#include <cuda_runtime.h>
#include <cuda_bf16.h>
#include <cstdint>

// Problem constants
#define MM   32
#define BB   1000
#define H1   512
#define H2   2048
#define DD   3072

#define X1_ROWS 2048   // interleaved: row 2b = h_b, row 2b+1 = t_b (b<1024, pads 0)
#define T2_ROWS 1024
#define NPART   512

// ---------------------------------------------------------------------------
// Static device scratch.
// ---------------------------------------------------------------------------
__device__ __align__(16) __nv_bfloat16 g_X1hi[X1_ROWS * H1];
__device__ __align__(16) __nv_bfloat16 g_X1lo[X1_ROWS * H1];
__device__ __align__(16) __nv_bfloat16 g_W2thi[H2 * H1];       // [N=2048,K=512]
__device__ __align__(16) __nv_bfloat16 g_W2tlo[H2 * H1];
__device__ __align__(16) __nv_bfloat16 g_W3thi[DD * H2];       // [N=3072,K=2048]
__device__ __align__(16) __nv_bfloat16 g_W3tlo[DD * H2];
__device__ __align__(16) __nv_bfloat16 g_T2hi[T2_ROWS * H2];
__device__ __align__(16) __nv_bfloat16 g_T2lo[T2_ROWS * H2];
__device__ float g_part[NPART];

__device__ __forceinline__ uint32_t smem_u32(const void* p) {
    uint32_t a;
    asm("{ .reg .u64 t; cvta.to.shared.u64 t, %1; cvt.u32.u64 %0, t; }"
        : "=r"(a) : "l"(p));
    return a;
}
__device__ __forceinline__ void split_bf16(float x, __nv_bfloat16& hi, __nv_bfloat16& lo) {
    hi = __float2bfloat16_rn(x);
    lo = __float2bfloat16_rn(x - __bfloat162float(hi));
}

// ---------------------------------------------------------------------------
// K1: layer-1 forward + tangent -> interleaved bf16 hi/lo rows (2b, 2b+1).
// ---------------------------------------------------------------------------
__global__ void k_layer1(const float* __restrict__ c0,
                         const float* __restrict__ c1,
                         const float* __restrict__ interior,
                         const float* __restrict__ W1,
                         const float* __restrict__ b1) {
    int b = blockIdx.x;            // 0..1023
    if (b >= BB) {
        const __nv_bfloat16 z = __float2bfloat16(0.0f);
        for (int k = threadIdx.x; k < H1; k += blockDim.x) {
            g_X1hi[(2 * b) * H1 + k]     = z;
            g_X1lo[(2 * b) * H1 + k]     = z;
            g_X1hi[(2 * b + 1) * H1 + k] = z;
            g_X1lo[(2 * b + 1) * H1 + k] = z;
        }
        return;
    }
    __shared__ float zs[MM], ds[MM];
    if (threadIdx.x < MM) {
        int m = threadIdx.x;
        float zb = (b == 0)    ? c0[m] : interior[(b - 1) * MM + m];
        float cn = (b == BB-1) ? c1[m] : interior[b * MM + m];
        zs[m] = zb;
        ds[m] = cn - zb;
    }
    __syncthreads();
    for (int k = threadIdx.x; k < H1; k += blockDim.x) {
        float a = b1[k];
        float g = 0.0f;
        #pragma unroll
        for (int m = 0; m < MM; ++m) {
            float w = W1[m * H1 + k];
            a = fmaf(zs[m], w, a);
            g = fmaf(ds[m], w, g);
        }
        float h = fmaxf(a, 0.0f);
        float t = (a > 0.0f) ? g : 0.0f;
        __nv_bfloat16 hh, hl, th, tl;
        split_bf16(h, hh, hl);
        split_bf16(t, th, tl);
        g_X1hi[(2 * b) * H1 + k]     = hh;
        g_X1lo[(2 * b) * H1 + k]     = hl;
        g_X1hi[(2 * b + 1) * H1 + k] = th;
        g_X1lo[(2 * b + 1) * H1 + k] = tl;
    }
}

// ---------------------------------------------------------------------------
// Transpose + bf16-split:  W[K,N] fp32  ->  Thi/Tlo[N,K] bf16
// ---------------------------------------------------------------------------
__global__ void k_transpose_split(const float* __restrict__ W,
                                  __nv_bfloat16* __restrict__ Thi,
                                  __nv_bfloat16* __restrict__ Tlo,
                                  int K, int N) {
    __shared__ float tile[32][33];
    int n0 = blockIdx.x * 32;
    int k0 = blockIdx.y * 32;
    int tx = threadIdx.x, ty = threadIdx.y;
    #pragma unroll
    for (int r = 0; r < 32; r += 8)
        tile[ty + r][tx] = W[(size_t)(k0 + ty + r) * N + n0 + tx];
    __syncthreads();
    #pragma unroll
    for (int r = 0; r < 32; r += 8) {
        float x = tile[tx][ty + r];
        __nv_bfloat16 hi, lo;
        split_bf16(x, hi, lo);
        size_t o = (size_t)(n0 + ty + r) * K + k0 + tx;
        Thi[o] = hi;
        Tlo[o] = lo;
    }
}

// ---------------------------------------------------------------------------
// mma.sync bf16 GEMM, bf16x3 split folded as K3 = 3K, 5-stage cp.async.
// CTA 128x128, 4 warps, warp tile 64x64 (MMA:LDSM ratio 4.0).
// MODE 0: GEMM1 — fused ReLU-gate epilogue -> g_T2hi/lo (aux = b2).
// MODE 1: GEMM2 — fused sum-of-squares epilogue -> g_part[cta].
// ---------------------------------------------------------------------------
#define BM 128
#define BN 128
#define BK 32
#define LDSR 40                     // bf16/row (80 B) -> conflict-free ldmatrix
#define STAGES 5
#define TILE_B (BM * LDSR * 2)      // 10240 bytes per operand stage
#define SMEM_BYTES (2 * STAGES * TILE_B)   // 102400

#define LDSM_X4(d, addr)                                                     \
    asm volatile("ldmatrix.sync.aligned.m8n8.x4.shared.b16 {%0,%1,%2,%3}, [%4];" \
                 : "=r"((d)[0]), "=r"((d)[1]), "=r"((d)[2]), "=r"((d)[3])    \
                 : "r"(addr))

#define MMA_16816(ac, av, r0, r1)                                            \
    asm volatile(                                                            \
        "mma.sync.aligned.m16n8k16.row.col.f32.bf16.bf16.f32 "               \
        "{%0,%1,%2,%3}, {%4,%5,%6,%7}, {%8,%9}, {%0,%1,%2,%3};"              \
        : "+f"((ac)[0]), "+f"((ac)[1]), "+f"((ac)[2]), "+f"((ac)[3])         \
        : "r"((av)[0]), "r"((av)[1]), "r"((av)[2]), "r"((av)[3]),            \
          "r"(r0), "r"(r1))

template <int MODE>
__global__ void __launch_bounds__(128, 2)
k_mma_gemm(const __nv_bfloat16* __restrict__ Ahi, const __nv_bfloat16* __restrict__ Alo,
           const __nv_bfloat16* __restrict__ Bhi, const __nv_bfloat16* __restrict__ Blo,
           const float* __restrict__ aux,
           int K, int N, int KT) {          // KT = 3K/BK
    extern __shared__ char sm[];
    const uint32_t aBase = smem_u32(sm);
    const uint32_t bBase = aBase + STAGES * TILE_B;
    const uint32_t aEnd  = bBase;
    const uint32_t bEnd  = bBase + STAGES * TILE_B;

    const int tid  = threadIdx.x;
    const int lane = tid & 31;
    const int wid  = tid >> 5;        // 0..3
    const int wm   = wid >> 1;        // 0..1  (M, 64 rows)
    const int wn   = wid & 1;         // 0..1  (N, 64 cols)
    const int bCol = blockIdx.x * BN;
    const int bRow = blockIdx.y * BM;

    // ldmatrix lane offsets
    const uint32_t lrow = (uint32_t)(lane & 15);
    const uint32_t lcol = (uint32_t)((lane >> 4) * 8);
    uint32_t aOff[4], bOff[4];
    #pragma unroll
    for (int f = 0; f < 4; ++f) {
        aOff[f] = ((wm * 64 + f * 16 + lrow) * LDSR + lcol) * 2;
        bOff[f] = ((wn * 64 + f * 16 + lrow) * LDSR + lcol) * 2;
    }
    // cp.async: thread covers row tid (A and B), 4 x 16B chunks each
    const uint32_t stOff = (uint32_t)(tid * (LDSR * 2));

    auto load_tile = [&](int kt, uint32_t aDst, uint32_t bDst) {
        int seg = (kt * BK) / K;                      // 0,1,2
        const __nv_bfloat16* Ag = (seg < 2)  ? Ahi : Alo;
        const __nv_bfloat16* Bg = (seg == 1) ? Blo : Bhi;
        int kb = kt * BK - seg * K;
        const __nv_bfloat16* aSrc = Ag + (size_t)(bRow + tid) * K + kb;
        const __nv_bfloat16* bSrc = Bg + (size_t)(bCol + tid) * K + kb;
        #pragma unroll
        for (int c = 0; c < 4; ++c) {
            asm volatile("cp.async.cg.shared.global [%0], [%1], 16;"
                         :: "r"(aDst + stOff + c * 16), "l"(aSrc + c * 8) : "memory");
            asm volatile("cp.async.cg.shared.global [%0], [%1], 16;"
                         :: "r"(bDst + stOff + c * 16), "l"(bSrc + c * 8) : "memory");
        }
    };

    float acc[4][8][4];
    #pragma unroll
    for (int i = 0; i < 4; ++i)
        #pragma unroll
        for (int j = 0; j < 8; ++j)
            #pragma unroll
            for (int r = 0; r < 4; ++r) acc[i][j][r] = 0.0f;

    // Prologue: fill 4 stages
    #pragma unroll
    for (int s = 0; s < STAGES - 1; ++s) {
        load_tile(s, aBase + s * TILE_B, bBase + s * TILE_B);
        asm volatile("cp.async.commit_group;" ::: "memory");
    }

    uint32_t rdA = aBase, rdB = bBase;
    uint32_t wrA = aBase + (STAGES - 1) * TILE_B;
    uint32_t wrB = bBase + (STAGES - 1) * TILE_B;

    for (int kt = 0; kt < KT; ++kt) {
        asm volatile("cp.async.wait_group %0;" :: "n"(STAGES - 2) : "memory");
        __syncthreads();
        if (kt + STAGES - 1 < KT) load_tile(kt + STAGES - 1, wrA, wrB);
        asm volatile("cp.async.commit_group;" ::: "memory");
        wrA += TILE_B; if (wrA == aEnd) wrA = aBase;
        wrB += TILE_B; if (wrB == bEnd) wrB = bBase;

        // ks=0 frags, then prefetch ks=16 A during ks0 MMAs, then ks=16 B.
        uint32_t a0[4][4], b0[4][4], a1[4][4], b1[4][4];
        #pragma unroll
        for (int f = 0; f < 4; ++f) LDSM_X4(a0[f], rdA + aOff[f]);
        #pragma unroll
        for (int f = 0; f < 4; ++f) LDSM_X4(b0[f], rdB + bOff[f]);
        #pragma unroll
        for (int f = 0; f < 4; ++f) LDSM_X4(a1[f], rdA + aOff[f] + 32);

        #pragma unroll
        for (int mf = 0; mf < 4; ++mf)
            #pragma unroll
            for (int g = 0; g < 4; ++g) {
                MMA_16816(acc[mf][2 * g],     a0[mf], b0[g][0], b0[g][2]);
                MMA_16816(acc[mf][2 * g + 1], a0[mf], b0[g][1], b0[g][3]);
            }

        #pragma unroll
        for (int f = 0; f < 4; ++f) LDSM_X4(b1[f], rdB + bOff[f] + 32);

        #pragma unroll
        for (int mf = 0; mf < 4; ++mf)
            #pragma unroll
            for (int g = 0; g < 4; ++g) {
                MMA_16816(acc[mf][2 * g],     a1[mf], b1[g][0], b1[g][2]);
                MMA_16816(acc[mf][2 * g + 1], a1[mf], b1[g][1], b1[g][3]);
            }

        rdA += TILE_B; if (rdA == aEnd) rdA = aBase;
        rdB += TILE_B; if (rdB == bEnd) rdB = bBase;
    }

    if (MODE == 0) {
        // Fused gate epilogue. Row r = bRow + wm*64 + mf*16 + half*8 + q,
        // parity of r = parity of q -> shfl_xor(4) pairs rows 2b / 2b+1.
        const int q    = lane >> 2;
        const bool odd = (q & 1) != 0;
        const int cB   = bCol + wn * 64 + (lane & 3) * 2;
        #pragma unroll
        for (int nf = 0; nf < 8; ++nf) {
            const int c = cB + nf * 8;
            const float2 b2v = *(const float2*)&aux[c];
            #pragma unroll
            for (int mf = 0; mf < 4; ++mf) {
                #pragma unroll
                for (int half = 0; half < 2; ++half) {
                    float x = acc[mf][nf][half * 2 + 0];
                    float y = acc[mf][nf][half * 2 + 1];
                    int fl = ((x + b2v.x) > 0.0f ? 1 : 0) |
                             ((y + b2v.y) > 0.0f ? 2 : 0);
                    int pf = __shfl_xor_sync(0xFFFFFFFFu, fl, 4);
                    if (odd) {
                        int r = bRow + wm * 64 + mf * 16 + half * 8 + q;
                        int tb = r >> 1;
                        float tx = (pf & 1) ? x : 0.0f;
                        float ty = (pf & 2) ? y : 0.0f;
                        __nv_bfloat16 hx, lx, hy, ly;
                        split_bf16(tx, hx, lx);
                        split_bf16(ty, hy, ly);
                        __nv_bfloat162 h2; h2.x = hx; h2.y = hy;
                        __nv_bfloat162 l2; l2.x = lx; l2.y = ly;
                        *(__nv_bfloat162*)&g_T2hi[(size_t)tb * H2 + c] = h2;
                        *(__nv_bfloat162*)&g_T2lo[(size_t)tb * H2 + c] = l2;
                    }
                }
            }
        }
    } else {
        // Fused sum-of-squares epilogue (deterministic).
        float s = 0.0f;
        #pragma unroll
        for (int mf = 0; mf < 4; ++mf)
            #pragma unroll
            for (int nf = 0; nf < 8; ++nf)
                #pragma unroll
                for (int r = 0; r < 4; ++r) {
                    float v = acc[mf][nf][r];
                    s = fmaf(v, v, s);
                }
        #pragma unroll
        for (int o = 16; o > 0; o >>= 1)
            s += __shfl_xor_sync(0xFFFFFFFFu, s, o);
        __syncthreads();
        float* red = (float*)sm;
        if (lane == 0) red[wid] = s;
        __syncthreads();
        if (tid == 0) {
            float tot = red[0] + red[1] + red[2] + red[3];
            g_part[blockIdx.y * gridDim.x + blockIdx.x] = tot;
        }
    }
}

// ---------------------------------------------------------------------------
// Final deterministic sum over n partials.
// ---------------------------------------------------------------------------
__global__ void k_finalize(float* __restrict__ out, int n) {
    __shared__ float red[256];
    float s = 0.0f;
    for (int i = threadIdx.x; i < n; i += 256) s += g_part[i];
    red[threadIdx.x] = s;
    __syncthreads();
    for (int o = 128; o > 0; o >>= 1) {
        if (threadIdx.x < o) red[threadIdx.x] += red[threadIdx.x + o];
        __syncthreads();
    }
    if (threadIdx.x == 0) out[0] = red[0];
}

// ---------------------------------------------------------------------------
// Launch.  Inputs: 0:c0 1:c1 2:interior 3:W1 4:b1 5:W2 6:b2 7:W3 8:b3(unused)
// ---------------------------------------------------------------------------
extern "C" void kernel_launch(void* const* d_in, const int* in_sizes, int n_in,
                              void* d_out, int out_size) {
    const float* c0       = (const float*)d_in[0];
    const float* c1       = (const float*)d_in[1];
    const float* interior = (const float*)d_in[2];
    const float* W1       = (const float*)d_in[3];
    const float* b1       = (const float*)d_in[4];
    const float* W2       = (const float*)d_in[5];
    const float* b2       = (const float*)d_in[6];
    const float* W3       = (const float*)d_in[7];
    (void)in_sizes; (void)n_in; (void)out_size;

    __nv_bfloat16 *X1hi, *X1lo, *W2thi, *W2tlo, *W3thi, *W3tlo, *T2hi, *T2lo;
    cudaGetSymbolAddress((void**)&X1hi,  g_X1hi);
    cudaGetSymbolAddress((void**)&X1lo,  g_X1lo);
    cudaGetSymbolAddress((void**)&W2thi, g_W2thi);
    cudaGetSymbolAddress((void**)&W2tlo, g_W2tlo);
    cudaGetSymbolAddress((void**)&W3thi, g_W3thi);
    cudaGetSymbolAddress((void**)&W3tlo, g_W3tlo);
    cudaGetSymbolAddress((void**)&T2hi,  g_T2hi);
    cudaGetSymbolAddress((void**)&T2lo,  g_T2lo);

    cudaFuncSetAttribute(k_mma_gemm<0>,
                         cudaFuncAttributeMaxDynamicSharedMemorySize, SMEM_BYTES);
    cudaFuncSetAttribute(k_mma_gemm<1>,
                         cudaFuncAttributeMaxDynamicSharedMemorySize, SMEM_BYTES);

    // Weight transpose+split
    k_transpose_split<<<dim3(H2 / 32, H1 / 32), dim3(32, 8)>>>(W2, W2thi, W2tlo, H1, H2);
    k_transpose_split<<<dim3(DD / 32, H2 / 32), dim3(32, 8)>>>(W3, W3thi, W3tlo, H2, DD);

    // L1 forward + tangent (interleaved rows, pads zeroed in-kernel)
    k_layer1<<<1024, 256>>>(c0, c1, interior, W1, b1);

    // GEMM1 + fused gate: X1(2048x512) @ W2t -> t2 bf16 splits
    k_mma_gemm<0><<<dim3(H2 / BN, X1_ROWS / BM), 128, SMEM_BYTES>>>(
        X1hi, X1lo, W2thi, W2tlo, b2, H1, H2, 3 * H1 / BK);

    // GEMM2 + fused sqsum: t2(1024x2048) @ W3t -> per-CTA partials
    const int g2x = DD / BN, g2y = T2_ROWS / BM;   // 24 x 8 = 192
    k_mma_gemm<1><<<dim3(g2x, g2y), 128, SMEM_BYTES>>>(
        T2hi, T2lo, W3thi, W3tlo, nullptr, H2, DD, 3 * H2 / BK);

    // energy = sum of partials (fixed order)
    k_finalize<<<1, 256>>>((float*)d_out, g2x * g2y);
}

// round 11
// speedup vs baseline: 1.2258x; 1.2258x over previous
#include <cuda_runtime.h>
#include <cuda_bf16.h>
#include <cstdint>

// Problem constants
#define MM   32
#define BB   1000
#define H1   512
#define H2   2048
#define DD   3072

#define X1_ROWS 2048   // interleaved: row 2b = h_b, row 2b+1 = t_b (b<1024, pads 0)
#define T2_ROWS 1024
#define NPART   512

// ---------------------------------------------------------------------------
// Static device scratch.
// ---------------------------------------------------------------------------
__device__ __align__(16) __nv_bfloat16 g_X1hi[X1_ROWS * H1];
__device__ __align__(16) __nv_bfloat16 g_X1lo[X1_ROWS * H1];
__device__ __align__(16) __nv_bfloat16 g_W2thi[H2 * H1];       // [N=2048,K=512]
__device__ __align__(16) __nv_bfloat16 g_W2tlo[H2 * H1];
__device__ __align__(16) __nv_bfloat16 g_W3thi[DD * H2];       // [N=3072,K=2048]
__device__ __align__(16) __nv_bfloat16 g_W3tlo[DD * H2];
__device__ __align__(16) __nv_bfloat16 g_T2hi[T2_ROWS * H2];
__device__ __align__(16) __nv_bfloat16 g_T2lo[T2_ROWS * H2];
__device__ float g_part[NPART];

__device__ __forceinline__ uint32_t smem_u32(const void* p) {
    uint32_t a;
    asm("{ .reg .u64 t; cvta.to.shared.u64 t, %1; cvt.u32.u64 %0, t; }"
        : "=r"(a) : "l"(p));
    return a;
}
__device__ __forceinline__ void split_bf16(float x, __nv_bfloat16& hi, __nv_bfloat16& lo) {
    hi = __float2bfloat16_rn(x);
    lo = __float2bfloat16_rn(x - __bfloat162float(hi));
}

// ---------------------------------------------------------------------------
// K1: layer-1 forward + tangent -> interleaved bf16 hi/lo rows (2b, 2b+1).
// ---------------------------------------------------------------------------
__global__ void k_layer1(const float* __restrict__ c0,
                         const float* __restrict__ c1,
                         const float* __restrict__ interior,
                         const float* __restrict__ W1,
                         const float* __restrict__ b1) {
    int b = blockIdx.x;            // 0..1023
    if (b >= BB) {
        const __nv_bfloat16 z = __float2bfloat16(0.0f);
        for (int k = threadIdx.x; k < H1; k += blockDim.x) {
            g_X1hi[(2 * b) * H1 + k]     = z;
            g_X1lo[(2 * b) * H1 + k]     = z;
            g_X1hi[(2 * b + 1) * H1 + k] = z;
            g_X1lo[(2 * b + 1) * H1 + k] = z;
        }
        return;
    }
    __shared__ float zs[MM], ds[MM];
    if (threadIdx.x < MM) {
        int m = threadIdx.x;
        float zb = (b == 0)    ? c0[m] : interior[(b - 1) * MM + m];
        float cn = (b == BB-1) ? c1[m] : interior[b * MM + m];
        zs[m] = zb;
        ds[m] = cn - zb;
    }
    __syncthreads();
    for (int k = threadIdx.x; k < H1; k += blockDim.x) {
        float a = b1[k];
        float g = 0.0f;
        #pragma unroll
        for (int m = 0; m < MM; ++m) {
            float w = W1[m * H1 + k];
            a = fmaf(zs[m], w, a);
            g = fmaf(ds[m], w, g);
        }
        float h = fmaxf(a, 0.0f);
        float t = (a > 0.0f) ? g : 0.0f;
        __nv_bfloat16 hh, hl, th, tl;
        split_bf16(h, hh, hl);
        split_bf16(t, th, tl);
        g_X1hi[(2 * b) * H1 + k]     = hh;
        g_X1lo[(2 * b) * H1 + k]     = hl;
        g_X1hi[(2 * b + 1) * H1 + k] = th;
        g_X1lo[(2 * b + 1) * H1 + k] = tl;
    }
}

// ---------------------------------------------------------------------------
// Transpose + bf16-split:  W[K,N] fp32  ->  Thi/Tlo[N,K] bf16
// ---------------------------------------------------------------------------
__global__ void k_transpose_split(const float* __restrict__ W,
                                  __nv_bfloat16* __restrict__ Thi,
                                  __nv_bfloat16* __restrict__ Tlo,
                                  int K, int N) {
    __shared__ float tile[32][33];
    int n0 = blockIdx.x * 32;
    int k0 = blockIdx.y * 32;
    int tx = threadIdx.x, ty = threadIdx.y;
    #pragma unroll
    for (int r = 0; r < 32; r += 8)
        tile[ty + r][tx] = W[(size_t)(k0 + ty + r) * N + n0 + tx];
    __syncthreads();
    #pragma unroll
    for (int r = 0; r < 32; r += 8) {
        float x = tile[tx][ty + r];
        __nv_bfloat16 hi, lo;
        split_bf16(x, hi, lo);
        size_t o = (size_t)(n0 + ty + r) * K + k0 + tx;
        Thi[o] = hi;
        Tlo[o] = lo;
    }
}

// ---------------------------------------------------------------------------
// mma.sync bf16 GEMM, bf16x3 split folded as K3 = 3K, 5-stage cp.async,
// cross-kt fragment double buffering (LDSM for kt+1 overlap MMA for kt).
// CTA 128x128, 8 warps, warp tile 32x64 (R9 layout).
// MODE 0: GEMM1 — fused ReLU-gate epilogue -> g_T2hi/lo (aux = b2).
// MODE 1: GEMM2 — fused sum-of-squares epilogue -> g_part[cta].
// ---------------------------------------------------------------------------
#define BM 128
#define BN 128
#define BK 32
#define LDSR 40                     // bf16/row (80 B) -> conflict-free ldmatrix
#define STAGES 5
#define TILE_B (BM * LDSR * 2)      // 10240 bytes per operand stage
#define SMEM_BYTES (2 * STAGES * TILE_B)   // 102400

#define LDSM_X4(d, addr)                                                     \
    asm volatile("ldmatrix.sync.aligned.m8n8.x4.shared.b16 {%0,%1,%2,%3}, [%4];" \
                 : "=r"((d)[0]), "=r"((d)[1]), "=r"((d)[2]), "=r"((d)[3])    \
                 : "r"(addr))

#define MMA_16816(ac, av, r0, r1)                                            \
    asm volatile(                                                            \
        "mma.sync.aligned.m16n8k16.row.col.f32.bf16.bf16.f32 "               \
        "{%0,%1,%2,%3}, {%4,%5,%6,%7}, {%8,%9}, {%0,%1,%2,%3};"              \
        : "+f"((ac)[0]), "+f"((ac)[1]), "+f"((ac)[2]), "+f"((ac)[3])         \
        : "r"((av)[0]), "r"((av)[1]), "r"((av)[2]), "r"((av)[3]),            \
          "r"(r0), "r"(r1))

struct Frags {
    uint32_t a[2][2][4];   // [ks][mf]
    uint32_t b[2][4][4];   // [ks][g]
};

__device__ __forceinline__ void load_frags(Frags& f, uint32_t rdA, uint32_t rdB,
                                           const uint32_t aOff0, const uint32_t aOff1,
                                           const uint32_t* bOff) {
    #pragma unroll
    for (int ks = 0; ks < 2; ++ks) {
        LDSM_X4(f.a[ks][0], rdA + aOff0 + ks * 32);
        LDSM_X4(f.a[ks][1], rdA + aOff1 + ks * 32);
        #pragma unroll
        for (int g = 0; g < 4; ++g)
            LDSM_X4(f.b[ks][g], rdB + bOff[g] + ks * 32);
    }
}

__device__ __forceinline__ void mma_frags(float acc[2][8][4], const Frags& f) {
    #pragma unroll
    for (int ks = 0; ks < 2; ++ks)
        #pragma unroll
        for (int mf = 0; mf < 2; ++mf)
            #pragma unroll
            for (int g = 0; g < 4; ++g) {
                MMA_16816(acc[mf][2 * g],     f.a[ks][mf], f.b[ks][g][0], f.b[ks][g][2]);
                MMA_16816(acc[mf][2 * g + 1], f.a[ks][mf], f.b[ks][g][1], f.b[ks][g][3]);
            }
}

template <int MODE>
__global__ void __launch_bounds__(256, 1)
k_mma_gemm(const __nv_bfloat16* __restrict__ Ahi, const __nv_bfloat16* __restrict__ Alo,
           const __nv_bfloat16* __restrict__ Bhi, const __nv_bfloat16* __restrict__ Blo,
           const float* __restrict__ aux,
           int K, int N, int KT) {          // KT = 3K/BK (even, >= 6)
    extern __shared__ char sm[];
    const uint32_t aBase = smem_u32(sm);
    const uint32_t bBase = aBase + STAGES * TILE_B;
    const uint32_t aEnd  = bBase;
    const uint32_t bEnd  = bBase + STAGES * TILE_B;

    const int tid  = threadIdx.x;
    const int lane = tid & 31;
    const int wid  = tid >> 5;
    const int wm   = wid >> 1;        // 0..3
    const int wn   = wid & 1;         // 0..1
    const int bCol = blockIdx.x * BN;
    const int bRow = blockIdx.y * BM;

    const int ldRow = tid >> 1;
    const int ldC0  = (tid & 1) * 2;

    const uint32_t lrow = (uint32_t)(lane & 15);
    const uint32_t lcol = (uint32_t)((lane >> 4) * 8);
    const uint32_t aOff0 = ((wm * 32 +  0 + lrow) * LDSR + lcol) * 2;
    const uint32_t aOff1 = ((wm * 32 + 16 + lrow) * LDSR + lcol) * 2;
    uint32_t bOff[4];
    #pragma unroll
    for (int g = 0; g < 4; ++g)
        bOff[g] = ((wn * 64 + g * 16 + lrow) * LDSR + lcol) * 2;
    const uint32_t stOff = (uint32_t)(ldRow * (LDSR * 2) + ldC0 * 16);

    auto load_tile = [&](int kt, uint32_t aDst, uint32_t bDst) {
        int seg = (kt * BK) / K;                      // 0,1,2
        const __nv_bfloat16* Ag = (seg < 2)  ? Ahi : Alo;
        const __nv_bfloat16* Bg = (seg == 1) ? Blo : Bhi;
        int kb = kt * BK - seg * K;
        const __nv_bfloat16* aSrc = Ag + (size_t)(bRow + ldRow) * K + kb + ldC0 * 8;
        const __nv_bfloat16* bSrc = Bg + (size_t)(bCol + ldRow) * K + kb + ldC0 * 8;
        asm volatile("cp.async.cg.shared.global [%0], [%1], 16;"
                     :: "r"(aDst + stOff), "l"(aSrc) : "memory");
        asm volatile("cp.async.cg.shared.global [%0], [%1], 16;"
                     :: "r"(aDst + stOff + 16), "l"(aSrc + 8) : "memory");
        asm volatile("cp.async.cg.shared.global [%0], [%1], 16;"
                     :: "r"(bDst + stOff), "l"(bSrc) : "memory");
        asm volatile("cp.async.cg.shared.global [%0], [%1], 16;"
                     :: "r"(bDst + stOff + 16), "l"(bSrc + 8) : "memory");
    };

    float acc[2][8][4];
    #pragma unroll
    for (int i = 0; i < 2; ++i)
        #pragma unroll
        for (int j = 0; j < 8; ++j)
            #pragma unroll
            for (int r = 0; r < 4; ++r) acc[i][j][r] = 0.0f;

    // Prologue: fill 4 stages, then load fragment set F0 from stage 0.
    #pragma unroll
    for (int s = 0; s < STAGES - 1; ++s) {
        load_tile(s, aBase + s * TILE_B, bBase + s * TILE_B);
        asm volatile("cp.async.commit_group;" ::: "memory");
    }
    asm volatile("cp.async.wait_group %0;" :: "n"(STAGES - 2) : "memory");
    __syncthreads();

    uint32_t rdA = aBase, rdB = bBase;                       // frag-read stage ptr
    uint32_t wrA = aBase + (STAGES - 1) * TILE_B;
    uint32_t wrB = bBase + (STAGES - 1) * TILE_B;

    Frags F0, F1;
    load_frags(F0, rdA, rdB, aOff0, aOff1, bOff);
    rdA += TILE_B; if (rdA == aEnd) rdA = aBase;
    rdB += TILE_B; if (rdB == bEnd) rdB = bBase;

    for (int kt = 0; kt < KT; kt += 2) {
        // ---- even half: MMA(F0), prefetch F1 (tile kt+1) ----
        __syncthreads();
        if (kt + STAGES - 1 < KT) load_tile(kt + STAGES - 1, wrA, wrB);
        asm volatile("cp.async.commit_group;" ::: "memory");
        wrA += TILE_B; if (wrA == aEnd) wrA = aBase;
        wrB += TILE_B; if (wrB == bEnd) wrB = bBase;
        asm volatile("cp.async.wait_group %0;" :: "n"(STAGES - 2) : "memory");

        load_frags(F1, rdA, rdB, aOff0, aOff1, bOff);        // tile kt+1
        rdA += TILE_B; if (rdA == aEnd) rdA = aBase;
        rdB += TILE_B; if (rdB == bEnd) rdB = bBase;
        mma_frags(acc, F0);                                   // tile kt

        // ---- odd half: MMA(F1), prefetch F0 (tile kt+2) ----
        __syncthreads();
        if (kt + STAGES < KT) load_tile(kt + STAGES, wrA, wrB);
        asm volatile("cp.async.commit_group;" ::: "memory");
        wrA += TILE_B; if (wrA == aEnd) wrA = aBase;
        wrB += TILE_B; if (wrB == bEnd) wrB = bBase;
        asm volatile("cp.async.wait_group %0;" :: "n"(STAGES - 2) : "memory");

        if (kt + 2 < KT) {
            load_frags(F0, rdA, rdB, aOff0, aOff1, bOff);    // tile kt+2
            rdA += TILE_B; if (rdA == aEnd) rdA = aBase;
            rdB += TILE_B; if (rdB == bEnd) rdB = bBase;
        }
        mma_frags(acc, F1);                                   // tile kt+1
    }

    if (MODE == 0) {
        // Fused gate epilogue (identical to R9).
        const int q    = lane >> 2;
        const bool odd = (q & 1) != 0;
        const int cB   = bCol + wn * 64 + (lane & 3) * 2;
        #pragma unroll
        for (int nf = 0; nf < 8; ++nf) {
            const int c = cB + nf * 8;
            const float2 b2v = *(const float2*)&aux[c];
            #pragma unroll
            for (int mf = 0; mf < 2; ++mf) {
                #pragma unroll
                for (int half = 0; half < 2; ++half) {
                    float x = acc[mf][nf][half * 2 + 0];
                    float y = acc[mf][nf][half * 2 + 1];
                    int fl = ((x + b2v.x) > 0.0f ? 1 : 0) |
                             ((y + b2v.y) > 0.0f ? 2 : 0);
                    int pf = __shfl_xor_sync(0xFFFFFFFFu, fl, 4);
                    if (odd) {
                        int r = bRow + wm * 32 + mf * 16 + half * 8 + q;
                        int tb = r >> 1;
                        float tx = (pf & 1) ? x : 0.0f;
                        float ty = (pf & 2) ? y : 0.0f;
                        __nv_bfloat16 hx, lx, hy, ly;
                        split_bf16(tx, hx, lx);
                        split_bf16(ty, hy, ly);
                        __nv_bfloat162 h2; h2.x = hx; h2.y = hy;
                        __nv_bfloat162 l2; l2.x = lx; l2.y = ly;
                        *(__nv_bfloat162*)&g_T2hi[(size_t)tb * H2 + c] = h2;
                        *(__nv_bfloat162*)&g_T2lo[(size_t)tb * H2 + c] = l2;
                    }
                }
            }
        }
    } else {
        // Fused sum-of-squares epilogue (identical to R9).
        float s = 0.0f;
        #pragma unroll
        for (int mf = 0; mf < 2; ++mf)
            #pragma unroll
            for (int nf = 0; nf < 8; ++nf)
                #pragma unroll
                for (int r = 0; r < 4; ++r) {
                    float v = acc[mf][nf][r];
                    s = fmaf(v, v, s);
                }
        #pragma unroll
        for (int o = 16; o > 0; o >>= 1)
            s += __shfl_xor_sync(0xFFFFFFFFu, s, o);
        __syncthreads();
        float* red = (float*)sm;
        if (lane == 0) red[wid] = s;
        __syncthreads();
        if (tid == 0) {
            float tot = 0.0f;
            #pragma unroll
            for (int w = 0; w < 8; ++w) tot += red[w];
            g_part[blockIdx.y * gridDim.x + blockIdx.x] = tot;
        }
    }
}

// ---------------------------------------------------------------------------
// Final deterministic sum over n partials.
// ---------------------------------------------------------------------------
__global__ void k_finalize(float* __restrict__ out, int n) {
    __shared__ float red[256];
    float s = 0.0f;
    for (int i = threadIdx.x; i < n; i += 256) s += g_part[i];
    red[threadIdx.x] = s;
    __syncthreads();
    for (int o = 128; o > 0; o >>= 1) {
        if (threadIdx.x < o) red[threadIdx.x] += red[threadIdx.x + o];
        __syncthreads();
    }
    if (threadIdx.x == 0) out[0] = red[0];
}

// ---------------------------------------------------------------------------
// Launch.  Inputs: 0:c0 1:c1 2:interior 3:W1 4:b1 5:W2 6:b2 7:W3 8:b3(unused)
// ---------------------------------------------------------------------------
extern "C" void kernel_launch(void* const* d_in, const int* in_sizes, int n_in,
                              void* d_out, int out_size) {
    const float* c0       = (const float*)d_in[0];
    const float* c1       = (const float*)d_in[1];
    const float* interior = (const float*)d_in[2];
    const float* W1       = (const float*)d_in[3];
    const float* b1       = (const float*)d_in[4];
    const float* W2       = (const float*)d_in[5];
    const float* b2       = (const float*)d_in[6];
    const float* W3       = (const float*)d_in[7];
    (void)in_sizes; (void)n_in; (void)out_size;

    __nv_bfloat16 *X1hi, *X1lo, *W2thi, *W2tlo, *W3thi, *W3tlo, *T2hi, *T2lo;
    cudaGetSymbolAddress((void**)&X1hi,  g_X1hi);
    cudaGetSymbolAddress((void**)&X1lo,  g_X1lo);
    cudaGetSymbolAddress((void**)&W2thi, g_W2thi);
    cudaGetSymbolAddress((void**)&W2tlo, g_W2tlo);
    cudaGetSymbolAddress((void**)&W3thi, g_W3thi);
    cudaGetSymbolAddress((void**)&W3tlo, g_W3tlo);
    cudaGetSymbolAddress((void**)&T2hi,  g_T2hi);
    cudaGetSymbolAddress((void**)&T2lo,  g_T2lo);

    cudaFuncSetAttribute(k_mma_gemm<0>,
                         cudaFuncAttributeMaxDynamicSharedMemorySize, SMEM_BYTES);
    cudaFuncSetAttribute(k_mma_gemm<1>,
                         cudaFuncAttributeMaxDynamicSharedMemorySize, SMEM_BYTES);

    // Weight transpose+split
    k_transpose_split<<<dim3(H2 / 32, H1 / 32), dim3(32, 8)>>>(W2, W2thi, W2tlo, H1, H2);
    k_transpose_split<<<dim3(DD / 32, H2 / 32), dim3(32, 8)>>>(W3, W3thi, W3tlo, H2, DD);

    // L1 forward + tangent (interleaved rows, pads zeroed in-kernel)
    k_layer1<<<1024, 256>>>(c0, c1, interior, W1, b1);

    // GEMM1 + fused gate: X1(2048x512) @ W2t -> t2 bf16 splits
    k_mma_gemm<0><<<dim3(H2 / BN, X1_ROWS / BM), 256, SMEM_BYTES>>>(
        X1hi, X1lo, W2thi, W2tlo, b2, H1, H2, 3 * H1 / BK);

    // GEMM2 + fused sqsum: t2(1024x2048) @ W3t -> per-CTA partials
    const int g2x = DD / BN, g2y = T2_ROWS / BM;   // 24 x 8 = 192
    k_mma_gemm<1><<<dim3(g2x, g2y), 256, SMEM_BYTES>>>(
        T2hi, T2lo, W3thi, W3tlo, nullptr, H2, DD, 3 * H2 / BK);

    // energy = sum of partials (fixed order)
    k_finalize<<<1, 256>>>((float*)d_out, g2x * g2y);
}

// round 12
// speedup vs baseline: 2.6910x; 2.1954x over previous
#include <cuda_runtime.h>
#include <cuda_bf16.h>
#include <cuda_fp16.h>
#include <cstdint>

// Problem constants
#define MM   32
#define BB   1000
#define H1   512
#define H2   2048
#define DD   3072

#define X1_ROWS 2048   // interleaved: row 2b = h_b, row 2b+1 = t_b (b<1024, pads 0)
#define T2_ROWS 1024
#define NPART   512

// ---------------------------------------------------------------------------
// Static device scratch.
// ---------------------------------------------------------------------------
__device__ __align__(16) __nv_bfloat16 g_X1hi[X1_ROWS * H1];
__device__ __align__(16) __nv_bfloat16 g_X1lo[X1_ROWS * H1];
__device__ __align__(16) __nv_bfloat16 g_W2thi[H2 * H1];       // [N=2048,K=512]
__device__ __align__(16) __nv_bfloat16 g_W2tlo[H2 * H1];
__device__ __align__(16) __half       g_W3th[DD * H2];         // [N=3072,K=2048] fp16
__device__ __align__(16) __half       g_T2h[T2_ROWS * H2];     // fp16 t2
__device__ float g_part[NPART];

__device__ __forceinline__ uint32_t smem_u32(const void* p) {
    uint32_t a;
    asm("{ .reg .u64 t; cvta.to.shared.u64 t, %1; cvt.u32.u64 %0, t; }"
        : "=r"(a) : "l"(p));
    return a;
}
__device__ __forceinline__ void split_bf16(float x, __nv_bfloat16& hi, __nv_bfloat16& lo) {
    hi = __float2bfloat16_rn(x);
    lo = __float2bfloat16_rn(x - __bfloat162float(hi));
}

// ---------------------------------------------------------------------------
// K1: layer-1 forward + tangent -> interleaved bf16 hi/lo rows (2b, 2b+1).
// ---------------------------------------------------------------------------
__global__ void k_layer1(const float* __restrict__ c0,
                         const float* __restrict__ c1,
                         const float* __restrict__ interior,
                         const float* __restrict__ W1,
                         const float* __restrict__ b1) {
    int b = blockIdx.x;            // 0..1023
    if (b >= BB) {
        const __nv_bfloat16 z = __float2bfloat16(0.0f);
        for (int k = threadIdx.x; k < H1; k += blockDim.x) {
            g_X1hi[(2 * b) * H1 + k]     = z;
            g_X1lo[(2 * b) * H1 + k]     = z;
            g_X1hi[(2 * b + 1) * H1 + k] = z;
            g_X1lo[(2 * b + 1) * H1 + k] = z;
        }
        return;
    }
    __shared__ float zs[MM], ds[MM];
    if (threadIdx.x < MM) {
        int m = threadIdx.x;
        float zb = (b == 0)    ? c0[m] : interior[(b - 1) * MM + m];
        float cn = (b == BB-1) ? c1[m] : interior[b * MM + m];
        zs[m] = zb;
        ds[m] = cn - zb;
    }
    __syncthreads();
    for (int k = threadIdx.x; k < H1; k += blockDim.x) {
        float a = b1[k];
        float g = 0.0f;
        #pragma unroll
        for (int m = 0; m < MM; ++m) {
            float w = W1[m * H1 + k];
            a = fmaf(zs[m], w, a);
            g = fmaf(ds[m], w, g);
        }
        float h = fmaxf(a, 0.0f);
        float t = (a > 0.0f) ? g : 0.0f;
        __nv_bfloat16 hh, hl, th, tl;
        split_bf16(h, hh, hl);
        split_bf16(t, th, tl);
        g_X1hi[(2 * b) * H1 + k]     = hh;
        g_X1lo[(2 * b) * H1 + k]     = hl;
        g_X1hi[(2 * b + 1) * H1 + k] = th;
        g_X1lo[(2 * b + 1) * H1 + k] = tl;
    }
}

// ---------------------------------------------------------------------------
// Transpose + bf16-split (W2): W[K,N] fp32 -> Thi/Tlo[N,K] bf16
// ---------------------------------------------------------------------------
__global__ void k_transpose_split(const float* __restrict__ W,
                                  __nv_bfloat16* __restrict__ Thi,
                                  __nv_bfloat16* __restrict__ Tlo,
                                  int K, int N) {
    __shared__ float tile[32][33];
    int n0 = blockIdx.x * 32;
    int k0 = blockIdx.y * 32;
    int tx = threadIdx.x, ty = threadIdx.y;
    #pragma unroll
    for (int r = 0; r < 32; r += 8)
        tile[ty + r][tx] = W[(size_t)(k0 + ty + r) * N + n0 + tx];
    __syncthreads();
    #pragma unroll
    for (int r = 0; r < 32; r += 8) {
        float x = tile[tx][ty + r];
        __nv_bfloat16 hi, lo;
        split_bf16(x, hi, lo);
        size_t o = (size_t)(n0 + ty + r) * K + k0 + tx;
        Thi[o] = hi;
        Tlo[o] = lo;
    }
}

// ---------------------------------------------------------------------------
// Transpose -> fp16 (W3): W[K,N] fp32 -> T[N,K] fp16
// ---------------------------------------------------------------------------
__global__ void k_transpose_half(const float* __restrict__ W,
                                 __half* __restrict__ T,
                                 int K, int N) {
    __shared__ float tile[32][33];
    int n0 = blockIdx.x * 32;
    int k0 = blockIdx.y * 32;
    int tx = threadIdx.x, ty = threadIdx.y;
    #pragma unroll
    for (int r = 0; r < 32; r += 8)
        tile[ty + r][tx] = W[(size_t)(k0 + ty + r) * N + n0 + tx];
    __syncthreads();
    #pragma unroll
    for (int r = 0; r < 32; r += 8) {
        size_t o = (size_t)(n0 + ty + r) * K + k0 + tx;
        T[o] = __float2half_rn(tile[tx][ty + r]);
    }
}

// ---------------------------------------------------------------------------
// mma.sync GEMM (R9 structure), 5-stage cp.async.
// MODE 0: bf16x3 split folded as K3=3K; fused ReLU-gate epilogue -> g_T2h fp16.
// MODE 1: single-pass fp16; fused sum-of-squares epilogue -> g_part[cta].
// CTA 128x128, 8 warps, warp tile 32x64.
// ---------------------------------------------------------------------------
#define BM 128
#define BN 128
#define BK 32
#define LDSR 40                     // 16-bit elems/row (80 B) -> conflict-free ldmatrix
#define STAGES 5
#define TILE_B (BM * LDSR * 2)      // 10240 bytes per operand stage
#define SMEM_BYTES (2 * STAGES * TILE_B)   // 102400

#define LDSM_X4(d, addr)                                                     \
    asm volatile("ldmatrix.sync.aligned.m8n8.x4.shared.b16 {%0,%1,%2,%3}, [%4];" \
                 : "=r"((d)[0]), "=r"((d)[1]), "=r"((d)[2]), "=r"((d)[3])    \
                 : "r"(addr))

#define MMA_BF16(ac, av, r0, r1)                                             \
    asm volatile(                                                            \
        "mma.sync.aligned.m16n8k16.row.col.f32.bf16.bf16.f32 "               \
        "{%0,%1,%2,%3}, {%4,%5,%6,%7}, {%8,%9}, {%0,%1,%2,%3};"              \
        : "+f"((ac)[0]), "+f"((ac)[1]), "+f"((ac)[2]), "+f"((ac)[3])         \
        : "r"((av)[0]), "r"((av)[1]), "r"((av)[2]), "r"((av)[3]),            \
          "r"(r0), "r"(r1))

#define MMA_FP16(ac, av, r0, r1)                                             \
    asm volatile(                                                            \
        "mma.sync.aligned.m16n8k16.row.col.f32.f16.f16.f32 "                 \
        "{%0,%1,%2,%3}, {%4,%5,%6,%7}, {%8,%9}, {%0,%1,%2,%3};"              \
        : "+f"((ac)[0]), "+f"((ac)[1]), "+f"((ac)[2]), "+f"((ac)[3])         \
        : "r"((av)[0]), "r"((av)[1]), "r"((av)[2]), "r"((av)[3]),            \
          "r"(r0), "r"(r1))

template <int MODE>
__global__ void __launch_bounds__(256, 2)
k_mma_gemm(const uint16_t* __restrict__ Ahi, const uint16_t* __restrict__ Alo,
           const uint16_t* __restrict__ Bhi, const uint16_t* __restrict__ Blo,
           const float* __restrict__ aux,
           int K, int N, int KT) {   // MODE0: KT = 3K/BK, MODE1: KT = K/BK
    extern __shared__ char sm[];
    const uint32_t aBase = smem_u32(sm);
    const uint32_t bBase = aBase + STAGES * TILE_B;
    const uint32_t aEnd  = bBase;
    const uint32_t bEnd  = bBase + STAGES * TILE_B;

    const int tid  = threadIdx.x;
    const int lane = tid & 31;
    const int wid  = tid >> 5;
    const int wm   = wid >> 1;        // 0..3
    const int wn   = wid & 1;         // 0..1
    const int bCol = blockIdx.x * BN;
    const int bRow = blockIdx.y * BM;

    const int ldRow = tid >> 1;
    const int ldC0  = (tid & 1) * 2;

    const uint32_t lrow = (uint32_t)(lane & 15);
    const uint32_t lcol = (uint32_t)((lane >> 4) * 8);
    const uint32_t aOff0 = ((wm * 32 +  0 + lrow) * LDSR + lcol) * 2;
    const uint32_t aOff1 = ((wm * 32 + 16 + lrow) * LDSR + lcol) * 2;
    uint32_t bOff[4];
    #pragma unroll
    for (int g = 0; g < 4; ++g)
        bOff[g] = ((wn * 64 + g * 16 + lrow) * LDSR + lcol) * 2;
    const uint32_t stOff = (uint32_t)(ldRow * (LDSR * 2) + ldC0 * 16);

    auto load_tile = [&](int kt, uint32_t aDst, uint32_t bDst) {
        const uint16_t *Ag, *Bg;
        int kb;
        if (MODE == 0) {
            int seg = (kt * BK) / K;                  // 0,1,2
            Ag = (seg < 2)  ? Ahi : Alo;
            Bg = (seg == 1) ? Blo : Bhi;
            kb = kt * BK - seg * K;
        } else {
            Ag = Ahi; Bg = Bhi; kb = kt * BK;
        }
        const uint16_t* aSrc = Ag + (size_t)(bRow + ldRow) * K + kb + ldC0 * 8;
        const uint16_t* bSrc = Bg + (size_t)(bCol + ldRow) * K + kb + ldC0 * 8;
        asm volatile("cp.async.cg.shared.global [%0], [%1], 16;"
                     :: "r"(aDst + stOff), "l"(aSrc) : "memory");
        asm volatile("cp.async.cg.shared.global [%0], [%1], 16;"
                     :: "r"(aDst + stOff + 16), "l"(aSrc + 8) : "memory");
        asm volatile("cp.async.cg.shared.global [%0], [%1], 16;"
                     :: "r"(bDst + stOff), "l"(bSrc) : "memory");
        asm volatile("cp.async.cg.shared.global [%0], [%1], 16;"
                     :: "r"(bDst + stOff + 16), "l"(bSrc + 8) : "memory");
    };

    float acc[2][8][4];
    #pragma unroll
    for (int i = 0; i < 2; ++i)
        #pragma unroll
        for (int j = 0; j < 8; ++j)
            #pragma unroll
            for (int r = 0; r < 4; ++r) acc[i][j][r] = 0.0f;

    // Prologue: fill 4 stages
    #pragma unroll
    for (int s = 0; s < STAGES - 1; ++s) {
        load_tile(s, aBase + s * TILE_B, bBase + s * TILE_B);
        asm volatile("cp.async.commit_group;" ::: "memory");
    }

    uint32_t rdA = aBase, rdB = bBase;
    uint32_t wrA = aBase + (STAGES - 1) * TILE_B;
    uint32_t wrB = bBase + (STAGES - 1) * TILE_B;

    for (int kt = 0; kt < KT; ++kt) {
        asm volatile("cp.async.wait_group %0;" :: "n"(STAGES - 2) : "memory");
        __syncthreads();
        if (kt + STAGES - 1 < KT) load_tile(kt + STAGES - 1, wrA, wrB);
        asm volatile("cp.async.commit_group;" ::: "memory");
        wrA += TILE_B; if (wrA == aEnd) wrA = aBase;
        wrB += TILE_B; if (wrB == bEnd) wrB = bBase;

        uint32_t a0[2][4], a1[2][4], b0[4][4], b1[4][4];
        LDSM_X4(a0[0], rdA + aOff0);
        LDSM_X4(a0[1], rdA + aOff1);
        LDSM_X4(b0[0], rdB + bOff[0]);
        LDSM_X4(b0[1], rdB + bOff[1]);
        LDSM_X4(b0[2], rdB + bOff[2]);
        LDSM_X4(b0[3], rdB + bOff[3]);
        LDSM_X4(a1[0], rdA + aOff0 + 32);
        LDSM_X4(a1[1], rdA + aOff1 + 32);

        #pragma unroll
        for (int mf = 0; mf < 2; ++mf)
            #pragma unroll
            for (int g = 0; g < 4; ++g) {
                if (MODE == 0) {
                    MMA_BF16(acc[mf][2 * g],     a0[mf], b0[g][0], b0[g][2]);
                    MMA_BF16(acc[mf][2 * g + 1], a0[mf], b0[g][1], b0[g][3]);
                } else {
                    MMA_FP16(acc[mf][2 * g],     a0[mf], b0[g][0], b0[g][2]);
                    MMA_FP16(acc[mf][2 * g + 1], a0[mf], b0[g][1], b0[g][3]);
                }
            }

        LDSM_X4(b1[0], rdB + bOff[0] + 32);
        LDSM_X4(b1[1], rdB + bOff[1] + 32);
        LDSM_X4(b1[2], rdB + bOff[2] + 32);
        LDSM_X4(b1[3], rdB + bOff[3] + 32);

        #pragma unroll
        for (int mf = 0; mf < 2; ++mf)
            #pragma unroll
            for (int g = 0; g < 4; ++g) {
                if (MODE == 0) {
                    MMA_BF16(acc[mf][2 * g],     a1[mf], b1[g][0], b1[g][2]);
                    MMA_BF16(acc[mf][2 * g + 1], a1[mf], b1[g][1], b1[g][3]);
                } else {
                    MMA_FP16(acc[mf][2 * g],     a1[mf], b1[g][0], b1[g][2]);
                    MMA_FP16(acc[mf][2 * g + 1], a1[mf], b1[g][1], b1[g][3]);
                }
            }

        rdA += TILE_B; if (rdA == aEnd) rdA = aBase;
        rdB += TILE_B; if (rdB == bEnd) rdB = bBase;
    }

    if (MODE == 0) {
        // Fused gate epilogue -> single fp16 t2.
        const int q    = lane >> 2;
        const bool odd = (q & 1) != 0;
        const int cB   = bCol + wn * 64 + (lane & 3) * 2;
        #pragma unroll
        for (int nf = 0; nf < 8; ++nf) {
            const int c = cB + nf * 8;
            const float2 b2v = *(const float2*)&aux[c];
            #pragma unroll
            for (int mf = 0; mf < 2; ++mf) {
                #pragma unroll
                for (int half = 0; half < 2; ++half) {
                    float x = acc[mf][nf][half * 2 + 0];
                    float y = acc[mf][nf][half * 2 + 1];
                    int fl = ((x + b2v.x) > 0.0f ? 1 : 0) |
                             ((y + b2v.y) > 0.0f ? 2 : 0);
                    int pf = __shfl_xor_sync(0xFFFFFFFFu, fl, 4);
                    if (odd) {
                        int r = bRow + wm * 32 + mf * 16 + half * 8 + q;
                        int tb = r >> 1;
                        float tx = (pf & 1) ? x : 0.0f;
                        float ty = (pf & 2) ? y : 0.0f;
                        __half2 h2;
                        h2.x = __float2half_rn(tx);
                        h2.y = __float2half_rn(ty);
                        *(__half2*)&g_T2h[(size_t)tb * H2 + c] = h2;
                    }
                }
            }
        }
    } else {
        // Fused sum-of-squares epilogue (deterministic).
        float s = 0.0f;
        #pragma unroll
        for (int mf = 0; mf < 2; ++mf)
            #pragma unroll
            for (int nf = 0; nf < 8; ++nf)
                #pragma unroll
                for (int r = 0; r < 4; ++r) {
                    float v = acc[mf][nf][r];
                    s = fmaf(v, v, s);
                }
        #pragma unroll
        for (int o = 16; o > 0; o >>= 1)
            s += __shfl_xor_sync(0xFFFFFFFFu, s, o);
        __syncthreads();
        float* red = (float*)sm;
        if (lane == 0) red[wid] = s;
        __syncthreads();
        if (tid == 0) {
            float tot = 0.0f;
            #pragma unroll
            for (int w = 0; w < 8; ++w) tot += red[w];
            g_part[blockIdx.y * gridDim.x + blockIdx.x] = tot;
        }
    }
}

// ---------------------------------------------------------------------------
// Final deterministic sum over n partials.
// ---------------------------------------------------------------------------
__global__ void k_finalize(float* __restrict__ out, int n) {
    __shared__ float red[256];
    float s = 0.0f;
    for (int i = threadIdx.x; i < n; i += 256) s += g_part[i];
    red[threadIdx.x] = s;
    __syncthreads();
    for (int o = 128; o > 0; o >>= 1) {
        if (threadIdx.x < o) red[threadIdx.x] += red[threadIdx.x + o];
        __syncthreads();
    }
    if (threadIdx.x == 0) out[0] = red[0];
}

// ---------------------------------------------------------------------------
// Launch.  Inputs: 0:c0 1:c1 2:interior 3:W1 4:b1 5:W2 6:b2 7:W3 8:b3(unused)
// ---------------------------------------------------------------------------
extern "C" void kernel_launch(void* const* d_in, const int* in_sizes, int n_in,
                              void* d_out, int out_size) {
    const float* c0       = (const float*)d_in[0];
    const float* c1       = (const float*)d_in[1];
    const float* interior = (const float*)d_in[2];
    const float* W1       = (const float*)d_in[3];
    const float* b1       = (const float*)d_in[4];
    const float* W2       = (const float*)d_in[5];
    const float* b2       = (const float*)d_in[6];
    const float* W3       = (const float*)d_in[7];
    (void)in_sizes; (void)n_in; (void)out_size;

    __nv_bfloat16 *X1hi, *X1lo, *W2thi, *W2tlo;
    __half *W3th, *T2h;
    cudaGetSymbolAddress((void**)&X1hi,  g_X1hi);
    cudaGetSymbolAddress((void**)&X1lo,  g_X1lo);
    cudaGetSymbolAddress((void**)&W2thi, g_W2thi);
    cudaGetSymbolAddress((void**)&W2tlo, g_W2tlo);
    cudaGetSymbolAddress((void**)&W3th,  g_W3th);
    cudaGetSymbolAddress((void**)&T2h,   g_T2h);

    cudaFuncSetAttribute(k_mma_gemm<0>,
                         cudaFuncAttributeMaxDynamicSharedMemorySize, SMEM_BYTES);
    cudaFuncSetAttribute(k_mma_gemm<1>,
                         cudaFuncAttributeMaxDynamicSharedMemorySize, SMEM_BYTES);

    // Weight prep: W2 -> bf16 split pair; W3 -> single fp16
    k_transpose_split<<<dim3(H2 / 32, H1 / 32), dim3(32, 8)>>>(W2, W2thi, W2tlo, H1, H2);
    k_transpose_half<<<dim3(DD / 32, H2 / 32), dim3(32, 8)>>>(W3, W3th, H2, DD);

    // L1 forward + tangent (interleaved rows, pads zeroed in-kernel)
    k_layer1<<<1024, 256>>>(c0, c1, interior, W1, b1);

    // GEMM1 (bf16x3) + fused gate: X1(2048x512) @ W2t -> t2 fp16
    k_mma_gemm<0><<<dim3(H2 / BN, X1_ROWS / BM), 256, SMEM_BYTES>>>(
        (const uint16_t*)X1hi, (const uint16_t*)X1lo,
        (const uint16_t*)W2thi, (const uint16_t*)W2tlo,
        b2, H1, H2, 3 * H1 / BK);

    // GEMM2 (single-pass fp16) + fused sqsum: t2(1024x2048) @ W3t -> partials
    const int g2x = DD / BN, g2y = T2_ROWS / BM;   // 24 x 8 = 192
    k_mma_gemm<1><<<dim3(g2x, g2y), 256, SMEM_BYTES>>>(
        (const uint16_t*)T2h, (const uint16_t*)T2h,
        (const uint16_t*)W3th, (const uint16_t*)W3th,
        nullptr, H2, DD, H2 / BK);

    // energy = sum of partials (fixed order)
    k_finalize<<<1, 256>>>((float*)d_out, g2x * g2y);
}

// round 13
// speedup vs baseline: 4.1804x; 1.5534x over previous
#include <cuda_runtime.h>
#include <cuda_fp16.h>
#include <cstdint>

// Problem constants
#define MM   32
#define BB   1000
#define H1   512
#define H2   2048
#define DD   3072

#define X1_ROWS 2048   // interleaved: row 2b = h_b, row 2b+1 = t_b (b<1024, pads 0)
#define T2_ROWS 1024
#define NPART   512

// ---------------------------------------------------------------------------
// Static device scratch (all fp16 now).
// ---------------------------------------------------------------------------
__device__ __align__(16) __half g_X1h[X1_ROWS * H1];    // 2 MB
__device__ __align__(16) __half g_W2th[H2 * H1];        // [N=2048,K=512]  2 MB
__device__ __align__(16) __half g_W3th[DD * H2];        // [N=3072,K=2048] 12 MB
__device__ __align__(16) __half g_T2h[T2_ROWS * H2];    // 4 MB
__device__ float g_part[NPART];

__device__ __forceinline__ uint32_t smem_u32(const void* p) {
    uint32_t a;
    asm("{ .reg .u64 t; cvta.to.shared.u64 t, %1; cvt.u32.u64 %0, t; }"
        : "=r"(a) : "l"(p));
    return a;
}

// ---------------------------------------------------------------------------
// K1: layer-1 forward + tangent -> interleaved fp16 rows (2b = h, 2b+1 = t).
// ---------------------------------------------------------------------------
__global__ void k_layer1(const float* __restrict__ c0,
                         const float* __restrict__ c1,
                         const float* __restrict__ interior,
                         const float* __restrict__ W1,
                         const float* __restrict__ b1) {
    int b = blockIdx.x;            // 0..1023
    if (b >= BB) {
        const __half z = __float2half(0.0f);
        for (int k = threadIdx.x; k < H1; k += blockDim.x) {
            g_X1h[(2 * b) * H1 + k]     = z;
            g_X1h[(2 * b + 1) * H1 + k] = z;
        }
        return;
    }
    __shared__ float zs[MM], ds[MM];
    if (threadIdx.x < MM) {
        int m = threadIdx.x;
        float zb = (b == 0)    ? c0[m] : interior[(b - 1) * MM + m];
        float cn = (b == BB-1) ? c1[m] : interior[b * MM + m];
        zs[m] = zb;
        ds[m] = cn - zb;
    }
    __syncthreads();
    for (int k = threadIdx.x; k < H1; k += blockDim.x) {
        float a = b1[k];
        float g = 0.0f;
        #pragma unroll
        for (int m = 0; m < MM; ++m) {
            float w = W1[m * H1 + k];
            a = fmaf(zs[m], w, a);
            g = fmaf(ds[m], w, g);
        }
        float h = fmaxf(a, 0.0f);
        float t = (a > 0.0f) ? g : 0.0f;
        g_X1h[(2 * b) * H1 + k]     = __float2half_rn(h);
        g_X1h[(2 * b + 1) * H1 + k] = __float2half_rn(t);
    }
}

// ---------------------------------------------------------------------------
// Transpose -> fp16:  W[K,N] fp32 -> T[N,K] fp16
// ---------------------------------------------------------------------------
__global__ void k_transpose_half(const float* __restrict__ W,
                                 __half* __restrict__ T,
                                 int K, int N) {
    __shared__ float tile[32][33];
    int n0 = blockIdx.x * 32;
    int k0 = blockIdx.y * 32;
    int tx = threadIdx.x, ty = threadIdx.y;
    #pragma unroll
    for (int r = 0; r < 32; r += 8)
        tile[ty + r][tx] = W[(size_t)(k0 + ty + r) * N + n0 + tx];
    __syncthreads();
    #pragma unroll
    for (int r = 0; r < 32; r += 8) {
        size_t o = (size_t)(n0 + ty + r) * K + k0 + tx;
        T[o] = __float2half_rn(tile[tx][ty + r]);
    }
}

// ---------------------------------------------------------------------------
// Single-pass fp16 mma.sync GEMM, 5-stage cp.async (R12 mainloop structure).
// Template: MODE 0 = gate epilogue (BNT must be 128); MODE 1 = sqsum epilogue.
//           BNT = N tile width (128 or 64).
// CTA tile 128 x BNT, 8 warps, warp tile 32 x (BNT/2).
// ---------------------------------------------------------------------------
#define BM 128
#define BK 32
#define LDSR 40                     // 16-bit elems/row (80 B) -> conflict-free ldmatrix
#define STAGES 5
#define TILE_A (BM * LDSR * 2)      // 10240 bytes per A stage

#define LDSM_X4(d, addr)                                                     \
    asm volatile("ldmatrix.sync.aligned.m8n8.x4.shared.b16 {%0,%1,%2,%3}, [%4];" \
                 : "=r"((d)[0]), "=r"((d)[1]), "=r"((d)[2]), "=r"((d)[3])    \
                 : "r"(addr))

#define MMA_FP16(ac, av, r0, r1)                                             \
    asm volatile(                                                            \
        "mma.sync.aligned.m16n8k16.row.col.f32.f16.f16.f32 "                 \
        "{%0,%1,%2,%3}, {%4,%5,%6,%7}, {%8,%9}, {%0,%1,%2,%3};"              \
        : "+f"((ac)[0]), "+f"((ac)[1]), "+f"((ac)[2]), "+f"((ac)[3])         \
        : "r"((av)[0]), "r"((av)[1]), "r"((av)[2]), "r"((av)[3]),            \
          "r"(r0), "r"(r1))

template <int MODE, int BNT>
__global__ void __launch_bounds__(256, 2)
k_mma_gemm(const uint16_t* __restrict__ A, const uint16_t* __restrict__ B,
           const float* __restrict__ aux,   // MODE0: b2;  MODE1: unused
           int K, int KT) {                 // KT = K/BK
    constexpr int TILE_BB = BNT * LDSR * 2;       // B stage bytes
    constexpr int G  = BNT / 32;                  // ldsm.x4 B groups per warp
    constexpr int NF = BNT / 16;                  // n8 acc frags per warp

    extern __shared__ char sm[];
    const uint32_t aBase = smem_u32(sm);
    const uint32_t aEnd  = aBase + STAGES * TILE_A;
    const uint32_t bBase = aEnd;
    const uint32_t bEnd  = bBase + STAGES * TILE_BB;

    const int tid  = threadIdx.x;
    const int lane = tid & 31;
    const int wid  = tid >> 5;
    const int wm   = wid >> 1;        // 0..3  (32 rows each)
    const int wn   = wid & 1;         // 0..1  (BNT/2 cols each)
    const int bCol = blockIdx.x * BNT;
    const int bRow = blockIdx.y * BM;

    // A loader: row = tid/2, two 16B chunks
    const int rowA = tid >> 1;
    const int cA0  = (tid & 1) * 2;
    const uint32_t stOffA = (uint32_t)(rowA * (LDSR * 2) + cA0 * 16);
    // B loader
    const int rowB = (BNT == 128) ? (tid >> 1) : (tid >> 2);
    const int cB0  = (BNT == 128) ? ((tid & 1) * 2) : (tid & 3);
    const uint32_t stOffB = (uint32_t)(rowB * (LDSR * 2) + cB0 * 16);

    const uint32_t lrow = (uint32_t)(lane & 15);
    const uint32_t lcol = (uint32_t)((lane >> 4) * 8);
    const uint32_t aOff0 = ((wm * 32 +  0 + lrow) * LDSR + lcol) * 2;
    const uint32_t aOff1 = ((wm * 32 + 16 + lrow) * LDSR + lcol) * 2;
    uint32_t bOff[G];
    #pragma unroll
    for (int g = 0; g < G; ++g)
        bOff[g] = ((wn * (BNT / 2) + g * 16 + lrow) * LDSR + lcol) * 2;

    auto load_tile = [&](int kt, uint32_t aDst, uint32_t bDst) {
        int kb = kt * BK;
        const uint16_t* aSrc = A + (size_t)(bRow + rowA) * K + kb + cA0 * 8;
        asm volatile("cp.async.cg.shared.global [%0], [%1], 16;"
                     :: "r"(aDst + stOffA), "l"(aSrc) : "memory");
        asm volatile("cp.async.cg.shared.global [%0], [%1], 16;"
                     :: "r"(aDst + stOffA + 16), "l"(aSrc + 8) : "memory");
        const uint16_t* bSrc = B + (size_t)(bCol + rowB) * K + kb + cB0 * 8;
        asm volatile("cp.async.cg.shared.global [%0], [%1], 16;"
                     :: "r"(bDst + stOffB), "l"(bSrc) : "memory");
        if (BNT == 128) {
            asm volatile("cp.async.cg.shared.global [%0], [%1], 16;"
                         :: "r"(bDst + stOffB + 16), "l"(bSrc + 8) : "memory");
        }
    };

    float acc[2][NF][4];
    #pragma unroll
    for (int i = 0; i < 2; ++i)
        #pragma unroll
        for (int j = 0; j < NF; ++j)
            #pragma unroll
            for (int r = 0; r < 4; ++r) acc[i][j][r] = 0.0f;

    // Prologue: fill 4 stages
    #pragma unroll
    for (int s = 0; s < STAGES - 1; ++s) {
        load_tile(s, aBase + s * TILE_A, bBase + s * TILE_BB);
        asm volatile("cp.async.commit_group;" ::: "memory");
    }

    uint32_t rdA = aBase, rdB = bBase;
    uint32_t wrA = aBase + (STAGES - 1) * TILE_A;
    uint32_t wrB = bBase + (STAGES - 1) * TILE_BB;

    for (int kt = 0; kt < KT; ++kt) {
        asm volatile("cp.async.wait_group %0;" :: "n"(STAGES - 2) : "memory");
        __syncthreads();
        if (kt + STAGES - 1 < KT) load_tile(kt + STAGES - 1, wrA, wrB);
        asm volatile("cp.async.commit_group;" ::: "memory");
        wrA += TILE_A;  if (wrA == aEnd) wrA = aBase;
        wrB += TILE_BB; if (wrB == bEnd) wrB = bBase;

        uint32_t a0[2][4], a1[2][4], b0[G][4], b1[G][4];
        LDSM_X4(a0[0], rdA + aOff0);
        LDSM_X4(a0[1], rdA + aOff1);
        #pragma unroll
        for (int g = 0; g < G; ++g) LDSM_X4(b0[g], rdB + bOff[g]);
        LDSM_X4(a1[0], rdA + aOff0 + 32);
        LDSM_X4(a1[1], rdA + aOff1 + 32);

        #pragma unroll
        for (int mf = 0; mf < 2; ++mf)
            #pragma unroll
            for (int g = 0; g < G; ++g) {
                MMA_FP16(acc[mf][2 * g],     a0[mf], b0[g][0], b0[g][2]);
                MMA_FP16(acc[mf][2 * g + 1], a0[mf], b0[g][1], b0[g][3]);
            }

        #pragma unroll
        for (int g = 0; g < G; ++g) LDSM_X4(b1[g], rdB + bOff[g] + 32);

        #pragma unroll
        for (int mf = 0; mf < 2; ++mf)
            #pragma unroll
            for (int g = 0; g < G; ++g) {
                MMA_FP16(acc[mf][2 * g],     a1[mf], b1[g][0], b1[g][2]);
                MMA_FP16(acc[mf][2 * g + 1], a1[mf], b1[g][1], b1[g][3]);
            }

        rdA += TILE_A;  if (rdA == aEnd) rdA = aBase;
        rdB += TILE_BB; if (rdB == bEnd) rdB = bBase;
    }

    if (MODE == 0) {
        // Fused gate epilogue (BNT == 128). Even rows carry a2-source (fwd),
        // odd rows the tangent; shfl_xor(4) pairs them.
        static_assert(MODE != 0 || BNT == 128, "gate epilogue assumes BNT=128");
        const int q    = lane >> 2;
        const bool odd = (q & 1) != 0;
        const int cB   = bCol + wn * 64 + (lane & 3) * 2;
        #pragma unroll
        for (int nf = 0; nf < NF; ++nf) {
            const int c = cB + nf * 8;
            const float2 b2v = *(const float2*)&aux[c];
            #pragma unroll
            for (int mf = 0; mf < 2; ++mf) {
                #pragma unroll
                for (int half = 0; half < 2; ++half) {
                    float x = acc[mf][nf][half * 2 + 0];
                    float y = acc[mf][nf][half * 2 + 1];
                    int fl = ((x + b2v.x) > 0.0f ? 1 : 0) |
                             ((y + b2v.y) > 0.0f ? 2 : 0);
                    int pf = __shfl_xor_sync(0xFFFFFFFFu, fl, 4);
                    if (odd) {
                        int r = bRow + wm * 32 + mf * 16 + half * 8 + q;
                        int tb = r >> 1;
                        float tx = (pf & 1) ? x : 0.0f;
                        float ty = (pf & 2) ? y : 0.0f;
                        __half2 h2;
                        h2.x = __float2half_rn(tx);
                        h2.y = __float2half_rn(ty);
                        *(__half2*)&g_T2h[(size_t)tb * H2 + c] = h2;
                    }
                }
            }
        }
    } else {
        // Fused sum-of-squares epilogue (deterministic).
        float s = 0.0f;
        #pragma unroll
        for (int mf = 0; mf < 2; ++mf)
            #pragma unroll
            for (int nf = 0; nf < NF; ++nf)
                #pragma unroll
                for (int r = 0; r < 4; ++r) {
                    float v = acc[mf][nf][r];
                    s = fmaf(v, v, s);
                }
        #pragma unroll
        for (int o = 16; o > 0; o >>= 1)
            s += __shfl_xor_sync(0xFFFFFFFFu, s, o);
        __syncthreads();
        float* red = (float*)sm;
        if (lane == 0) red[wid] = s;
        __syncthreads();
        if (tid == 0) {
            float tot = 0.0f;
            #pragma unroll
            for (int w = 0; w < 8; ++w) tot += red[w];
            g_part[blockIdx.y * gridDim.x + blockIdx.x] = tot;
        }
    }
}

// ---------------------------------------------------------------------------
// Final deterministic sum over n partials.
// ---------------------------------------------------------------------------
__global__ void k_finalize(float* __restrict__ out, int n) {
    __shared__ float red[256];
    float s = 0.0f;
    for (int i = threadIdx.x; i < n; i += 256) s += g_part[i];
    red[threadIdx.x] = s;
    __syncthreads();
    for (int o = 128; o > 0; o >>= 1) {
        if (threadIdx.x < o) red[threadIdx.x] += red[threadIdx.x + o];
        __syncthreads();
    }
    if (threadIdx.x == 0) out[0] = red[0];
}

// ---------------------------------------------------------------------------
// Launch.  Inputs: 0:c0 1:c1 2:interior 3:W1 4:b1 5:W2 6:b2 7:W3 8:b3(unused)
// ---------------------------------------------------------------------------
#define SMEM_M0 (STAGES * (TILE_A + 128 * LDSR * 2))   // 102400
#define SMEM_M1 (STAGES * (TILE_A + 64 * LDSR * 2))    // 76800

extern "C" void kernel_launch(void* const* d_in, const int* in_sizes, int n_in,
                              void* d_out, int out_size) {
    const float* c0       = (const float*)d_in[0];
    const float* c1       = (const float*)d_in[1];
    const float* interior = (const float*)d_in[2];
    const float* W1       = (const float*)d_in[3];
    const float* b1       = (const float*)d_in[4];
    const float* W2       = (const float*)d_in[5];
    const float* b2       = (const float*)d_in[6];
    const float* W3       = (const float*)d_in[7];
    (void)in_sizes; (void)n_in; (void)out_size;

    __half *X1h, *W2th, *W3th, *T2h;
    cudaGetSymbolAddress((void**)&X1h,  g_X1h);
    cudaGetSymbolAddress((void**)&W2th, g_W2th);
    cudaGetSymbolAddress((void**)&W3th, g_W3th);
    cudaGetSymbolAddress((void**)&T2h,  g_T2h);

    cudaFuncSetAttribute((const void*)k_mma_gemm<0, 128>,
                         cudaFuncAttributeMaxDynamicSharedMemorySize, SMEM_M0);
    cudaFuncSetAttribute((const void*)k_mma_gemm<1, 64>,
                         cudaFuncAttributeMaxDynamicSharedMemorySize, SMEM_M1);

    // Weight prep: W2, W3 -> transposed fp16
    k_transpose_half<<<dim3(H2 / 32, H1 / 32), dim3(32, 8)>>>(W2, W2th, H1, H2);
    k_transpose_half<<<dim3(DD / 32, H2 / 32), dim3(32, 8)>>>(W3, W3th, H2, DD);

    // L1 forward + tangent (interleaved fp16 rows, pads zeroed in-kernel)
    k_layer1<<<1024, 256>>>(c0, c1, interior, W1, b1);

    // GEMM1 (fp16) + fused gate: X1(2048x512) @ W2t -> t2 fp16
    k_mma_gemm<0, 128><<<dim3(H2 / 128, X1_ROWS / BM), 256, SMEM_M0>>>(
        (const uint16_t*)X1h, (const uint16_t*)W2th, b2, H1, H1 / BK);

    // GEMM2 (fp16, 128x64 tiles for wave balance) + fused sqsum
    const int g2x = DD / 64, g2y = T2_ROWS / BM;   // 48 x 8 = 384
    k_mma_gemm<1, 64><<<dim3(g2x, g2y), 256, SMEM_M1>>>(
        (const uint16_t*)T2h, (const uint16_t*)W3th, nullptr, H2, H2 / BK);

    // energy = sum of partials (fixed order)
    k_finalize<<<1, 256>>>((float*)d_out, g2x * g2y);
}

// round 14
// speedup vs baseline: 4.2309x; 1.0121x over previous
#include <cuda_runtime.h>
#include <cuda_fp16.h>
#include <cstdint>

// Problem constants
#define MM   32
#define BB   1000
#define H1   512
#define H2   2048
#define DD   3072

#define X1_ROWS 2048   // interleaved: row 2b = h_b, row 2b+1 = t_b (b<1024, pads 0)
#define T2_ROWS 1024
#define NPART   512

// ---------------------------------------------------------------------------
// Static device scratch (all fp16).
// ---------------------------------------------------------------------------
__device__ __align__(16) __half g_X1h[X1_ROWS * H1];    // 2 MB
__device__ __align__(16) __half g_W2th[H2 * H1];        // [N=2048,K=512]  2 MB
__device__ __align__(16) __half g_W3th[DD * H2];        // [N=3072,K=2048] 12 MB
__device__ __align__(16) __half g_T2h[T2_ROWS * H2];    // 4 MB
__device__ float g_part[NPART];

__device__ __forceinline__ uint32_t smem_u32(const void* p) {
    uint32_t a;
    asm("{ .reg .u64 t; cvta.to.shared.u64 t, %1; cvt.u32.u64 %0, t; }"
        : "=r"(a) : "l"(p));
    return a;
}

// ---------------------------------------------------------------------------
// K1: layer-1 forward + tangent -> interleaved fp16 rows (2b = h, 2b+1 = t).
// ---------------------------------------------------------------------------
__global__ void k_layer1(const float* __restrict__ c0,
                         const float* __restrict__ c1,
                         const float* __restrict__ interior,
                         const float* __restrict__ W1,
                         const float* __restrict__ b1) {
    int b = blockIdx.x;            // 0..1023
    if (b >= BB) {
        const __half z = __float2half(0.0f);
        for (int k = threadIdx.x; k < H1; k += blockDim.x) {
            g_X1h[(2 * b) * H1 + k]     = z;
            g_X1h[(2 * b + 1) * H1 + k] = z;
        }
        return;
    }
    __shared__ float zs[MM], ds[MM];
    if (threadIdx.x < MM) {
        int m = threadIdx.x;
        float zb = (b == 0)    ? c0[m] : interior[(b - 1) * MM + m];
        float cn = (b == BB-1) ? c1[m] : interior[b * MM + m];
        zs[m] = zb;
        ds[m] = cn - zb;
    }
    __syncthreads();
    for (int k = threadIdx.x; k < H1; k += blockDim.x) {
        float a = b1[k];
        float g = 0.0f;
        #pragma unroll
        for (int m = 0; m < MM; ++m) {
            float w = W1[m * H1 + k];
            a = fmaf(zs[m], w, a);
            g = fmaf(ds[m], w, g);
        }
        float h = fmaxf(a, 0.0f);
        float t = (a > 0.0f) ? g : 0.0f;
        g_X1h[(2 * b) * H1 + k]     = __float2half_rn(h);
        g_X1h[(2 * b + 1) * H1 + k] = __float2half_rn(t);
    }
}

// ---------------------------------------------------------------------------
// Transpose -> fp16:  W[K,N] fp32 -> T[N,K] fp16
// ---------------------------------------------------------------------------
__global__ void k_transpose_half(const float* __restrict__ W,
                                 __half* __restrict__ T,
                                 int K, int N) {
    __shared__ float tile[32][33];
    int n0 = blockIdx.x * 32;
    int k0 = blockIdx.y * 32;
    int tx = threadIdx.x, ty = threadIdx.y;
    #pragma unroll
    for (int r = 0; r < 32; r += 8)
        tile[ty + r][tx] = W[(size_t)(k0 + ty + r) * N + n0 + tx];
    __syncthreads();
    #pragma unroll
    for (int r = 0; r < 32; r += 8) {
        size_t o = (size_t)(n0 + ty + r) * K + k0 + tx;
        T[o] = __float2half_rn(tile[tx][ty + r]);
    }
}

// ---------------------------------------------------------------------------
// Single-pass fp16 mma.sync GEMM, multi-stage cp.async.
// Template: MODE 0 = gate epilogue; MODE 1 = sqsum epilogue.
//           BNT = N tile width; NST = pipeline stages; MINB = min blocks/SM.
// CTA tile 128 x BNT, 8 warps, warp tile 32 x (BNT/2).
// ---------------------------------------------------------------------------
#define BM 128
#define BK 32
#define LDSR 40                     // 16-bit elems/row (80 B) -> conflict-free ldmatrix
#define TILE_A (BM * LDSR * 2)      // 10240 bytes per A stage

#define LDSM_X4(d, addr)                                                     \
    asm volatile("ldmatrix.sync.aligned.m8n8.x4.shared.b16 {%0,%1,%2,%3}, [%4];" \
                 : "=r"((d)[0]), "=r"((d)[1]), "=r"((d)[2]), "=r"((d)[3])    \
                 : "r"(addr))

#define MMA_FP16(ac, av, r0, r1)                                             \
    asm volatile(                                                            \
        "mma.sync.aligned.m16n8k16.row.col.f32.f16.f16.f32 "                 \
        "{%0,%1,%2,%3}, {%4,%5,%6,%7}, {%8,%9}, {%0,%1,%2,%3};"              \
        : "+f"((ac)[0]), "+f"((ac)[1]), "+f"((ac)[2]), "+f"((ac)[3])         \
        : "r"((av)[0]), "r"((av)[1]), "r"((av)[2]), "r"((av)[3]),            \
          "r"(r0), "r"(r1))

template <int MODE, int BNT, int NST, int MINB>
__global__ void __launch_bounds__(256, MINB)
k_mma_gemm(const uint16_t* __restrict__ A, const uint16_t* __restrict__ B,
           const float* __restrict__ aux,   // MODE0: b2;  MODE1: unused
           int K, int KT) {                 // KT = K/BK
    constexpr int TILE_BB = BNT * LDSR * 2;       // B stage bytes
    constexpr int G  = BNT / 32;                  // ldsm.x4 B groups per warp
    constexpr int NF = BNT / 16;                  // n8 acc frags per warp

    extern __shared__ char sm[];
    const uint32_t aBase = smem_u32(sm);
    const uint32_t aEnd  = aBase + NST * TILE_A;
    const uint32_t bBase = aEnd;
    const uint32_t bEnd  = bBase + NST * TILE_BB;

    const int tid  = threadIdx.x;
    const int lane = tid & 31;
    const int wid  = tid >> 5;
    const int wm   = wid >> 1;        // 0..3  (32 rows each)
    const int wn   = wid & 1;         // 0..1  (BNT/2 cols each)
    const int bCol = blockIdx.x * BNT;
    const int bRow = blockIdx.y * BM;

    // A loader: row = tid/2, two 16B chunks
    const int rowA = tid >> 1;
    const int cA0  = (tid & 1) * 2;
    const uint32_t stOffA = (uint32_t)(rowA * (LDSR * 2) + cA0 * 16);
    // B loader
    const int rowB = (BNT == 128) ? (tid >> 1) : (tid >> 2);
    const int cB0  = (BNT == 128) ? ((tid & 1) * 2) : (tid & 3);
    const uint32_t stOffB = (uint32_t)(rowB * (LDSR * 2) + cB0 * 16);

    const uint32_t lrow = (uint32_t)(lane & 15);
    const uint32_t lcol = (uint32_t)((lane >> 4) * 8);
    const uint32_t aOff0 = ((wm * 32 +  0 + lrow) * LDSR + lcol) * 2;
    const uint32_t aOff1 = ((wm * 32 + 16 + lrow) * LDSR + lcol) * 2;
    uint32_t bOff[G];
    #pragma unroll
    for (int g = 0; g < G; ++g)
        bOff[g] = ((wn * (BNT / 2) + g * 16 + lrow) * LDSR + lcol) * 2;

    auto load_tile = [&](int kt, uint32_t aDst, uint32_t bDst) {
        int kb = kt * BK;
        const uint16_t* aSrc = A + (size_t)(bRow + rowA) * K + kb + cA0 * 8;
        asm volatile("cp.async.cg.shared.global [%0], [%1], 16;"
                     :: "r"(aDst + stOffA), "l"(aSrc) : "memory");
        asm volatile("cp.async.cg.shared.global [%0], [%1], 16;"
                     :: "r"(aDst + stOffA + 16), "l"(aSrc + 8) : "memory");
        const uint16_t* bSrc = B + (size_t)(bCol + rowB) * K + kb + cB0 * 8;
        asm volatile("cp.async.cg.shared.global [%0], [%1], 16;"
                     :: "r"(bDst + stOffB), "l"(bSrc) : "memory");
        if (BNT == 128) {
            asm volatile("cp.async.cg.shared.global [%0], [%1], 16;"
                         :: "r"(bDst + stOffB + 16), "l"(bSrc + 8) : "memory");
        }
    };

    float acc[2][NF][4];
    #pragma unroll
    for (int i = 0; i < 2; ++i)
        #pragma unroll
        for (int j = 0; j < NF; ++j)
            #pragma unroll
            for (int r = 0; r < 4; ++r) acc[i][j][r] = 0.0f;

    // Prologue: fill NST-1 stages
    #pragma unroll
    for (int s = 0; s < NST - 1; ++s) {
        load_tile(s, aBase + s * TILE_A, bBase + s * TILE_BB);
        asm volatile("cp.async.commit_group;" ::: "memory");
    }

    uint32_t rdA = aBase, rdB = bBase;
    uint32_t wrA = aBase + (NST - 1) * TILE_A;
    uint32_t wrB = bBase + (NST - 1) * TILE_BB;

    for (int kt = 0; kt < KT; ++kt) {
        asm volatile("cp.async.wait_group %0;" :: "n"(NST - 2) : "memory");
        __syncthreads();
        if (kt + NST - 1 < KT) load_tile(kt + NST - 1, wrA, wrB);
        asm volatile("cp.async.commit_group;" ::: "memory");
        wrA += TILE_A;  if (wrA == aEnd) wrA = aBase;
        wrB += TILE_BB; if (wrB == bEnd) wrB = bBase;

        uint32_t a0[2][4], a1[2][4], b0[G][4], b1[G][4];
        LDSM_X4(a0[0], rdA + aOff0);
        LDSM_X4(a0[1], rdA + aOff1);
        #pragma unroll
        for (int g = 0; g < G; ++g) LDSM_X4(b0[g], rdB + bOff[g]);
        LDSM_X4(a1[0], rdA + aOff0 + 32);
        LDSM_X4(a1[1], rdA + aOff1 + 32);

        #pragma unroll
        for (int mf = 0; mf < 2; ++mf)
            #pragma unroll
            for (int g = 0; g < G; ++g) {
                MMA_FP16(acc[mf][2 * g],     a0[mf], b0[g][0], b0[g][2]);
                MMA_FP16(acc[mf][2 * g + 1], a0[mf], b0[g][1], b0[g][3]);
            }

        #pragma unroll
        for (int g = 0; g < G; ++g) LDSM_X4(b1[g], rdB + bOff[g] + 32);

        #pragma unroll
        for (int mf = 0; mf < 2; ++mf)
            #pragma unroll
            for (int g = 0; g < G; ++g) {
                MMA_FP16(acc[mf][2 * g],     a1[mf], b1[g][0], b1[g][2]);
                MMA_FP16(acc[mf][2 * g + 1], a1[mf], b1[g][1], b1[g][3]);
            }

        rdA += TILE_A;  if (rdA == aEnd) rdA = aBase;
        rdB += TILE_BB; if (rdB == bEnd) rdB = bBase;
    }

    if (MODE == 0) {
        // Fused gate epilogue (row pairing is N-width independent).
        const int q    = lane >> 2;
        const bool odd = (q & 1) != 0;
        const int cB   = bCol + wn * (BNT / 2) + (lane & 3) * 2;
        #pragma unroll
        for (int nf = 0; nf < NF; ++nf) {
            const int c = cB + nf * 8;
            const float2 b2v = *(const float2*)&aux[c];
            #pragma unroll
            for (int mf = 0; mf < 2; ++mf) {
                #pragma unroll
                for (int half = 0; half < 2; ++half) {
                    float x = acc[mf][nf][half * 2 + 0];
                    float y = acc[mf][nf][half * 2 + 1];
                    int fl = ((x + b2v.x) > 0.0f ? 1 : 0) |
                             ((y + b2v.y) > 0.0f ? 2 : 0);
                    int pf = __shfl_xor_sync(0xFFFFFFFFu, fl, 4);
                    if (odd) {
                        int r = bRow + wm * 32 + mf * 16 + half * 8 + q;
                        int tb = r >> 1;
                        float tx = (pf & 1) ? x : 0.0f;
                        float ty = (pf & 2) ? y : 0.0f;
                        __half2 h2;
                        h2.x = __float2half_rn(tx);
                        h2.y = __float2half_rn(ty);
                        *(__half2*)&g_T2h[(size_t)tb * H2 + c] = h2;
                    }
                }
            }
        }
    } else {
        // Fused sum-of-squares epilogue (deterministic).
        float s = 0.0f;
        #pragma unroll
        for (int mf = 0; mf < 2; ++mf)
            #pragma unroll
            for (int nf = 0; nf < NF; ++nf)
                #pragma unroll
                for (int r = 0; r < 4; ++r) {
                    float v = acc[mf][nf][r];
                    s = fmaf(v, v, s);
                }
        #pragma unroll
        for (int o = 16; o > 0; o >>= 1)
            s += __shfl_xor_sync(0xFFFFFFFFu, s, o);
        __syncthreads();
        float* red = (float*)sm;
        if (lane == 0) red[wid] = s;
        __syncthreads();
        if (tid == 0) {
            float tot = 0.0f;
            #pragma unroll
            for (int w = 0; w < 8; ++w) tot += red[w];
            g_part[blockIdx.y * gridDim.x + blockIdx.x] = tot;
        }
    }
}

// ---------------------------------------------------------------------------
// Final deterministic sum over n partials.
// ---------------------------------------------------------------------------
__global__ void k_finalize(float* __restrict__ out, int n) {
    __shared__ float red[256];
    float s = 0.0f;
    for (int i = threadIdx.x; i < n; i += 256) s += g_part[i];
    red[threadIdx.x] = s;
    __syncthreads();
    for (int o = 128; o > 0; o >>= 1) {
        if (threadIdx.x < o) red[threadIdx.x] += red[threadIdx.x + o];
        __syncthreads();
    }
    if (threadIdx.x == 0) out[0] = red[0];
}

// ---------------------------------------------------------------------------
// Launch.  Inputs: 0:c0 1:c1 2:interior 3:W1 4:b1 5:W2 6:b2 7:W3 8:b3(unused)
// ---------------------------------------------------------------------------
#define SMEM_M0 (5 * (TILE_A + 128 * LDSR * 2))   // 102400, 5 stages, 2 CTAs/SM
#define SMEM_M1 (4 * (TILE_A + 64 * LDSR * 2))    // 61440,  4 stages, 3 CTAs/SM

extern "C" void kernel_launch(void* const* d_in, const int* in_sizes, int n_in,
                              void* d_out, int out_size) {
    const float* c0       = (const float*)d_in[0];
    const float* c1       = (const float*)d_in[1];
    const float* interior = (const float*)d_in[2];
    const float* W1       = (const float*)d_in[3];
    const float* b1       = (const float*)d_in[4];
    const float* W2       = (const float*)d_in[5];
    const float* b2       = (const float*)d_in[6];
    const float* W3       = (const float*)d_in[7];
    (void)in_sizes; (void)n_in; (void)out_size;

    __half *X1h, *W2th, *W3th, *T2h;
    cudaGetSymbolAddress((void**)&X1h,  g_X1h);
    cudaGetSymbolAddress((void**)&W2th, g_W2th);
    cudaGetSymbolAddress((void**)&W3th, g_W3th);
    cudaGetSymbolAddress((void**)&T2h,  g_T2h);

    cudaFuncSetAttribute((const void*)k_mma_gemm<0, 128, 5, 2>,
                         cudaFuncAttributeMaxDynamicSharedMemorySize, SMEM_M0);
    cudaFuncSetAttribute((const void*)k_mma_gemm<1, 64, 4, 3>,
                         cudaFuncAttributeMaxDynamicSharedMemorySize, SMEM_M1);

    // Weight prep: W2, W3 -> transposed fp16
    k_transpose_half<<<dim3(H2 / 32, H1 / 32), dim3(32, 8)>>>(W2, W2th, H1, H2);
    k_transpose_half<<<dim3(DD / 32, H2 / 32), dim3(32, 8)>>>(W3, W3th, H2, DD);

    // L1 forward + tangent (interleaved fp16 rows, pads zeroed in-kernel)
    k_layer1<<<1024, 256>>>(c0, c1, interior, W1, b1);

    // GEMM1 (fp16, unchanged R13 config) + fused gate
    k_mma_gemm<0, 128, 5, 2><<<dim3(H2 / 128, X1_ROWS / BM), 256, SMEM_M0>>>(
        (const uint16_t*)X1h, (const uint16_t*)W2th, b2, H1, H1 / BK);

    // GEMM2 (fp16, 4 stages, 3 CTAs/SM target) + fused sqsum
    const int g2x = DD / 64, g2y = T2_ROWS / BM;   // 48 x 8 = 384
    k_mma_gemm<1, 64, 4, 3><<<dim3(g2x, g2y), 256, SMEM_M1>>>(
        (const uint16_t*)T2h, (const uint16_t*)W3th, nullptr, H2, H2 / BK);

    // energy = sum of partials (fixed order)
    k_finalize<<<1, 256>>>((float*)d_out, g2x * g2y);
}